// round 15
// baseline (speedup 1.0000x reference)
#include <cuda_runtime.h>
#include <cuda_fp16.h>
#include <math.h>
#include <cstdint>

#define DIMD   1024
#define HEADS  16
#define DH     64
#define INNER  1024
#define BATCH  4
#define SEQ    2048
#define ROWS   (BATCH*SEQ)      // 8192
#define QKVW   (3*INNER)        // 3072

// Scratch (device globals). All fp16, NATURAL layouts.
__device__ __half g_xn  [ROWS*DIMD];
__device__ __half g_qkv [ROWS*QKVW];
__device__ __half g_att [ROWS*INNER];
__device__ __half g_wqkv[DIMD*QKVW];    // [K][N] natural (fp16 copy)
__device__ __half g_wout[INNER*DIMD];   // [K][N] natural (fp16 copy)

__device__ __forceinline__ void mma_f16(float* d, const uint32_t* a, const uint32_t* b) {
    asm volatile(
        "mma.sync.aligned.m16n8k16.row.col.f32.f16.f16.f32 "
        "{%0,%1,%2,%3}, {%4,%5,%6,%7}, {%8,%9}, {%0,%1,%2,%3};"
        : "+f"(d[0]), "+f"(d[1]), "+f"(d[2]), "+f"(d[3])
        : "r"(a[0]), "r"(a[1]), "r"(a[2]), "r"(a[3]), "r"(b[0]), "r"(b[1]));
}

__device__ __forceinline__ void ldmx4(uint32_t& r0, uint32_t& r1, uint32_t& r2,
                                      uint32_t& r3, uint32_t addr) {
    asm volatile("ldmatrix.sync.aligned.m8n8.x4.shared.b16 {%0,%1,%2,%3}, [%4];"
                 : "=r"(r0), "=r"(r1), "=r"(r2), "=r"(r3) : "r"(addr));
}
__device__ __forceinline__ void ldmx4t(uint32_t& r0, uint32_t& r1, uint32_t& r2,
                                       uint32_t& r3, uint32_t addr) {
    asm volatile("ldmatrix.sync.aligned.m8n8.x4.trans.shared.b16 {%0,%1,%2,%3}, [%4];"
                 : "=r"(r0), "=r"(r1), "=r"(r2), "=r"(r3) : "r"(addr));
}

__device__ __forceinline__ void cp_async16(uint32_t smem_dst, const void* gmem_src) {
    asm volatile("cp.async.cg.shared.global [%0], [%1], 16;" :: "r"(smem_dst), "l"(gmem_src));
}
#define CP_COMMIT() asm volatile("cp.async.commit_group;" ::: "memory")
#define CP_WAIT(n)  asm volatile("cp.async.wait_group %0;" :: "n"(n) : "memory")

__device__ __forceinline__ uint32_t h2u(__half2 h) { return *reinterpret_cast<uint32_t*>(&h); }
__device__ __forceinline__ uint32_t packh2(float a, float b) {
    return h2u(__floats2half2_rn(a, b));
}

// ===========================================================================
// LayerNorm: WARP-PER-ROW (8 rows/block, shuffle-only reduction, no smem).
// ===========================================================================
__global__ void ln_kernel(const float* __restrict__ x,
                          const float* __restrict__ gamma,
                          const float* __restrict__ beta,
                          __half* __restrict__ out) {
    int wid  = threadIdx.x >> 5;
    int lane = threadIdx.x & 31;
    int row  = blockIdx.x * 8 + wid;

    const float4* xr = reinterpret_cast<const float4*>(x + (size_t)row * DIMD);
    const float4* g4 = reinterpret_cast<const float4*>(gamma);
    const float4* b4 = reinterpret_cast<const float4*>(beta);

    float4 v[8];
    float s = 0.f, ss = 0.f;
    #pragma unroll
    for (int i = 0; i < 8; i++) {
        v[i] = xr[lane + i * 32];
        s  += v[i].x + v[i].y + v[i].z + v[i].w;
        ss += v[i].x*v[i].x + v[i].y*v[i].y + v[i].z*v[i].z + v[i].w*v[i].w;
    }
    #pragma unroll
    for (int o = 16; o > 0; o >>= 1) {
        s  += __shfl_xor_sync(0xFFFFFFFFu, s,  o);
        ss += __shfl_xor_sync(0xFFFFFFFFu, ss, o);
    }
    float mu   = s * (1.0f / DIMD);
    float var  = ss * (1.0f / DIMD) - mu * mu;
    float rstd = rsqrtf(var + 1e-5f);

    __half* orow = out + (size_t)row * DIMD;
    #pragma unroll
    for (int i = 0; i < 8; i++) {
        float4 g = g4[lane + i * 32];
        float4 b = b4[lane + i * 32];
        uint2 o2;
        o2.x = packh2((v[i].x - mu) * rstd * g.x + b.x, (v[i].y - mu) * rstd * g.y + b.y);
        o2.y = packh2((v[i].z - mu) * rstd * g.z + b.z, (v[i].w - mu) * rstd * g.w + b.w);
        *reinterpret_cast<uint2*>(orow + (lane + i * 32) * 4) = o2;
    }
}

// ===========================================================================
// Flat fp32 -> fp16 convert (weights), coalesced both sides.
// ===========================================================================
__global__ void convert_h(const float* __restrict__ in, __half* __restrict__ out, int n4) {
    int i = blockIdx.x * blockDim.x + threadIdx.x;
    if (i < n4) {
        float4 v = reinterpret_cast<const float4*>(in)[i];
        uint2 o2;
        o2.x = packh2(v.x, v.y);
        o2.y = packh2(v.z, v.w);
        *reinterpret_cast<uint2*>(out + (size_t)i * 4) = o2;
    }
}

// ===========================================================================
// fp16 mma.sync GEMM, cp.async 3-stage ring, one barrier per phase.
// C[M,Nn] = A[M,K] @ W[K,Nn]. A natural [M][K]; W natural [K][Nn].
// ===========================================================================
#define GBK   64
#define GSTR  72
#define BSTR  136
#define GTILEA (128 * GSTR)
#define GTILEB (64 * BSTR)
#define GEMM_SMEM ((3 * GTILEA + 3 * GTILEB) * 2)   // 107520 B

template <bool HALF_OUT>
__global__ __launch_bounds__(256, 2)
void gemm_f16(const __half* __restrict__ A, const __half* __restrict__ W,
              void* __restrict__ Cv, int M, int Nn, int K) {
    extern __shared__ __half smh[];

    int tid  = threadIdx.x;
    int lane = tid & 31;
    int wid  = tid >> 5;
    int wm   = wid >> 2;
    int wn   = wid & 3;

    const __half* Ab = A + (size_t)blockIdx.y * 128 * K;
    const __half* Wb = W + blockIdx.x * 128;

    float acc[4][4][4];
    #pragma unroll
    for (int i = 0; i < 4; i++)
        #pragma unroll
        for (int j = 0; j < 4; j++)
            #pragma unroll
            for (int k = 0; k < 4; k++) acc[i][j][k] = 0.f;

    const int nchunks = K / GBK;
    uint32_t smbase = (uint32_t)__cvta_generic_to_shared(smh);

    auto stage = [&](int c) {
        int buf = c % 3;
        uint32_t sA = smbase + (buf * GTILEA) * 2;
        uint32_t sB = smbase + (3 * GTILEA + buf * GTILEB) * 2;
        const __half* Ac = Ab + c * GBK;
        const __half* Wc = Wb + (size_t)(c * GBK) * Nn;
        #pragma unroll
        for (int i = 0; i < 4; i++) {
            int idx = i * 256 + tid;
            int m = idx >> 3, k8 = (idx & 7) << 3;
            cp_async16(sA + (m * GSTR + k8) * 2, Ac + (size_t)m * K + k8);
            int kr = idx >> 4, n8 = (idx & 15) << 3;
            cp_async16(sB + (kr * BSTR + n8) * 2, Wc + (size_t)kr * Nn + n8);
        }
    };

    stage(0); CP_COMMIT();
    stage(1); CP_COMMIT();

    int r  = lane >> 2;
    int cq = lane & 3;
    int arow = lane & 15, akoff = (lane >> 4) << 3;
    int sub = lane >> 3;
    int blb = ((sub & 1) * 8 + (lane & 7)) * BSTR + (sub >> 1) * 8;

    for (int c = 0; c < nchunks; c++) {
        if (c + 1 < nchunks) { CP_WAIT(1); } else { CP_WAIT(0); }
        __syncthreads();
        if (c + 2 < nchunks) { stage(c + 2); CP_COMMIT(); }

        int buf = c % 3;
        uint32_t sAu = smbase + (buf * GTILEA) * 2;
        uint32_t sBu = smbase + (3 * GTILEA + buf * GTILEB) * 2;

        #pragma unroll
        for (int ks = 0; ks < 4; ks++) {
            uint32_t a[4][4], b[2][4];
            #pragma unroll
            for (int mt = 0; mt < 4; mt++) {
                uint32_t addr = sAu + (((wm * 64 + mt * 16 + arow) * GSTR) + ks * 16 + akoff) * 2;
                ldmx4(a[mt][0], a[mt][1], a[mt][2], a[mt][3], addr);
            }
            #pragma unroll
            for (int np = 0; np < 2; np++) {
                uint32_t addr = sBu + (ks * 16 * BSTR + wn * 32 + np * 16 + blb) * 2;
                ldmx4t(b[np][0], b[np][1], b[np][2], b[np][3], addr);
            }
            #pragma unroll
            for (int mt = 0; mt < 4; mt++)
                #pragma unroll
                for (int nt = 0; nt < 4; nt++)
                    mma_f16(acc[mt][nt], a[mt], &b[nt >> 1][(nt & 1) * 2]);
        }
    }

    #pragma unroll
    for (int mt = 0; mt < 4; mt++) {
        int row0 = blockIdx.y * 128 + wm * 64 + mt * 16 + r;
        #pragma unroll
        for (int nt = 0; nt < 4; nt++) {
            int col0 = blockIdx.x * 128 + wn * 32 + nt * 8 + cq * 2;
            if (HALF_OUT) {
                __half* C = (__half*)Cv;
                *reinterpret_cast<uint32_t*>(C + (size_t)row0 * Nn + col0) =
                    packh2(acc[mt][nt][0], acc[mt][nt][1]);
                *reinterpret_cast<uint32_t*>(C + (size_t)(row0 + 8) * Nn + col0) =
                    packh2(acc[mt][nt][2], acc[mt][nt][3]);
            } else {
                float* C = (float*)Cv;
                *reinterpret_cast<float2*>(C + (size_t)row0 * Nn + col0) =
                    make_float2(acc[mt][nt][0], acc[mt][nt][1]);
                *reinterpret_cast<float2*>(C + (size_t)(row0 + 8) * Nn + col0) =
                    make_float2(acc[mt][nt][2], acc[mt][nt][3]);
            }
        }
    }
}

// ===========================================================================
// Flash attention fp16 mma, register-resident P, 2-stage ring, one barrier
// per phase, 2 CTAs/SM, exp2 softmax, diagonal-tile MMA skipping.
// ===========================================================================
#define KSTR 72
#define KTILE (64 * KSTR)
#define ASM_Q (4 * KTILE)
#define QSTR 72
#define ATTN_SMEM ((4 * KTILE + 128 * QSTR) * 2)   // 55296 B -> 2 CTAs/SM

__global__ __launch_bounds__(256, 2)
void attn_mma(const __half* __restrict__ qkv, __half* __restrict__ att) {
    extern __shared__ __half smh[];

    int tid = threadIdx.x, lane = tid & 31, wid = tid >> 5;
    int r = lane >> 2, cq = lane & 3;
    int qt = gridDim.x - 1 - blockIdx.x;     // longest tiles first
    int h = blockIdx.y, b = blockIdx.z;
    int q0 = qt * 128;

    const __half* qbase = qkv + (size_t)b * SEQ * QKVW + h * DH;
    const __half* kbase = qbase + INNER;
    const __half* vbase = qbase + 2 * INNER;

    uint32_t smb = (uint32_t)__cvta_generic_to_shared(smh);
    uint32_t sQu = smb + ASM_Q * 2;

    const int nchunk = 2 * qt + 2;

    auto stage = [&](int c) {
        int buf = c & 1;
        uint32_t sK = smb + (buf * KTILE) * 2;
        uint32_t sV = smb + ((2 + buf) * KTILE) * 2;
        const __half* kc = kbase + (size_t)c * 64 * QKVW;
        const __half* vc = vbase + (size_t)c * 64 * QKVW;
        #pragma unroll
        for (int i = 0; i < 2; i++) {
            int idx = i * 256 + tid;
            int row = idx >> 3, d8 = (idx & 7) << 3;
            cp_async16(sK + (row * KSTR + d8) * 2, kc + (size_t)row * QKVW + d8);
            cp_async16(sV + (row * KSTR + d8) * 2, vc + (size_t)row * QKVW + d8);
        }
    };

    #pragma unroll
    for (int i = 0; i < 4; i++) {
        int idx = i * 256 + tid;
        int row = idx >> 3, d8 = (idx & 7) << 3;
        cp_async16(sQu + (row * QSTR + d8) * 2, qbase + (size_t)(q0 + row) * QKVW + d8);
    }
    stage(0); CP_COMMIT();

    int arow = lane & 15, akoff = (lane >> 4) << 3;
    int brow = ((lane >> 4) << 3) + (lane & 7), bkoff = ((lane >> 3) & 1) << 3;
    int sub = lane >> 3;
    int vlb = ((sub & 1) * 8 + (lane & 7)) * KSTR + (sub >> 1) * 8;

    uint32_t qf[4][4];
    float m0 = -1e30f, m1 = -1e30f, l0 = 0.f, l1 = 0.f;
    float o[8][4];
    #pragma unroll
    for (int nt = 0; nt < 8; nt++)
        #pragma unroll
        for (int j = 0; j < 4; j++) o[nt][j] = 0.f;

    const __half2 qsc = __floats2half2_rn(0.125f * 1.44269504f, 0.125f * 1.44269504f);

    for (int c = 0; c < nchunk; c++) {
        CP_WAIT(0);
        __syncthreads();
        if (c + 1 < nchunk) { stage(c + 1); CP_COMMIT(); }

        if (c == 0) {
            #pragma unroll
            for (int kt = 0; kt < 4; kt++) {
                uint32_t addr = sQu + (((wid * 16 + arow) * QSTR) + kt * 16 + akoff) * 2;
                ldmx4(qf[kt][0], qf[kt][1], qf[kt][2], qf[kt][3], addr);
                #pragma unroll
                for (int j = 0; j < 4; j++)
                    qf[kt][j] = h2u(__hmul2(*reinterpret_cast<__half2*>(&qf[kt][j]), qsc));
            }
        }

        int buf = c & 1;
        uint32_t sKu = smb + (buf * KTILE) * 2;
        uint32_t sVu = smb + ((2 + buf) * KTILE) * 2;

        int wrow0 = q0 + wid * 16;
        int wrow_hi = wrow0 + 15;
        if (wrow_hi >= c * 64) {
            // ---- S = Q @ K^T (skip fully-masked np tiles on diagonal chunk)
            float s[8][4];
            #pragma unroll
            for (int nt = 0; nt < 8; nt++)
                #pragma unroll
                for (int j = 0; j < 4; j++) s[nt][j] = 0.f;
            #pragma unroll
            for (int np = 0; np < 4; np++) {
                if (c * 64 + np * 16 <= wrow_hi) {
                    #pragma unroll
                    for (int kt = 0; kt < 4; kt++) {
                        uint32_t b0, b1, b2, b3;
                        uint32_t addr = sKu + (((np * 16 + brow) * KSTR) + kt * 16 + bkoff) * 2;
                        ldmx4(b0, b1, b2, b3, addr);
                        uint32_t bfa[2] = { b0, b1 };
                        uint32_t bfb[2] = { b2, b3 };
                        mma_f16(s[2 * np],     qf[kt], bfa);
                        mma_f16(s[2 * np + 1], qf[kt], bfb);
                    }
                }
            }

            // ---- causal mask (covers skipped tiles too)
            if (c * 64 + 63 > wrow0) {
                int row_a = wrow0 + r, row_b = wrow0 + r + 8;
                #pragma unroll
                for (int nt = 0; nt < 8; nt++) {
                    int col = c * 64 + nt * 8 + 2 * cq;
                    if (col     > row_a) s[nt][0] = -1e30f;
                    if (col + 1 > row_a) s[nt][1] = -1e30f;
                    if (col     > row_b) s[nt][2] = -1e30f;
                    if (col + 1 > row_b) s[nt][3] = -1e30f;
                }
            }

            // ---- online softmax (base-2)
            float mt0 = -1e30f, mt1 = -1e30f;
            #pragma unroll
            for (int nt = 0; nt < 8; nt++) {
                mt0 = fmaxf(mt0, fmaxf(s[nt][0], s[nt][1]));
                mt1 = fmaxf(mt1, fmaxf(s[nt][2], s[nt][3]));
            }
            mt0 = fmaxf(mt0, __shfl_xor_sync(0xFFFFFFFFu, mt0, 1));
            mt0 = fmaxf(mt0, __shfl_xor_sync(0xFFFFFFFFu, mt0, 2));
            mt1 = fmaxf(mt1, __shfl_xor_sync(0xFFFFFFFFu, mt1, 1));
            mt1 = fmaxf(mt1, __shfl_xor_sync(0xFFFFFFFFu, mt1, 2));

            float mn0 = fmaxf(m0, mt0), mn1 = fmaxf(m1, mt1);
            float a0 = exp2f(m0 - mn0), a1 = exp2f(m1 - mn1);
            m0 = mn0; m1 = mn1;
            float rs0 = 0.f, rs1 = 0.f;
            #pragma unroll
            for (int nt = 0; nt < 8; nt++) {
                s[nt][0] = exp2f(s[nt][0] - mn0);
                s[nt][1] = exp2f(s[nt][1] - mn0);
                s[nt][2] = exp2f(s[nt][2] - mn1);
                s[nt][3] = exp2f(s[nt][3] - mn1);
                rs0 += s[nt][0] + s[nt][1];
                rs1 += s[nt][2] + s[nt][3];
            }
            rs0 += __shfl_xor_sync(0xFFFFFFFFu, rs0, 1);
            rs0 += __shfl_xor_sync(0xFFFFFFFFu, rs0, 2);
            rs1 += __shfl_xor_sync(0xFFFFFFFFu, rs1, 1);
            rs1 += __shfl_xor_sync(0xFFFFFFFFu, rs1, 2);
            l0 = l0 * a0 + rs0;
            l1 = l1 * a1 + rs1;
            #pragma unroll
            for (int nt = 0; nt < 8; nt++) {
                o[nt][0] *= a0; o[nt][1] *= a0;
                o[nt][2] *= a1; o[nt][3] *= a1;
            }

            // ---- O += P @ V (skip all-zero kt groups past the diagonal)
            #pragma unroll
            for (int kt = 0; kt < 4; kt++) {
                if (c * 64 + kt * 16 <= wrow_hi) {
                    uint32_t pf[4];
                    pf[0] = packh2(s[2 * kt][0],     s[2 * kt][1]);
                    pf[1] = packh2(s[2 * kt][2],     s[2 * kt][3]);
                    pf[2] = packh2(s[2 * kt + 1][0], s[2 * kt + 1][1]);
                    pf[3] = packh2(s[2 * kt + 1][2], s[2 * kt + 1][3]);
                    #pragma unroll
                    for (int ntp = 0; ntp < 4; ntp++) {
                        uint32_t b0a, b1a, b0b, b1b;
                        uint32_t addr = sVu + (vlb + kt * 16 * KSTR + ntp * 16) * 2;
                        ldmx4t(b0a, b1a, b0b, b1b, addr);
                        uint32_t bfa[2] = { b0a, b1a };
                        uint32_t bfb[2] = { b0b, b1b };
                        mma_f16(o[2 * ntp],     pf, bfa);
                        mma_f16(o[2 * ntp + 1], pf, bfb);
                    }
                }
            }
        }
    }

    float inv0 = 1.f / l0, inv1 = 1.f / l1;
    int row_a = q0 + wid * 16 + r, row_b = row_a + 8;
    #pragma unroll
    for (int nt = 0; nt < 8; nt++) {
        int col = h * DH + nt * 8 + 2 * cq;
        *reinterpret_cast<uint32_t*>(att + ((size_t)b * SEQ + row_a) * INNER + col) =
            packh2(o[nt][0] * inv0, o[nt][1] * inv0);
        *reinterpret_cast<uint32_t*>(att + ((size_t)b * SEQ + row_b) * INNER + col) =
            packh2(o[nt][2] * inv1, o[nt][3] * inv1);
    }
}

// ===========================================================================
extern "C" void kernel_launch(void* const* d_in, const int* in_sizes, int n_in,
                              void* d_out, int out_size) {
    const float* x     = (const float*)d_in[0];
    const float* gamma = (const float*)d_in[1];
    const float* beta  = (const float*)d_in[2];
    const float* w_qkv = (const float*)d_in[3];
    const float* w_out = (const float*)d_in[4];
    float* out = (float*)d_out;

    __half *xn, *qkv, *att, *wqkv, *wout;
    cudaGetSymbolAddress((void**)&xn,   g_xn);
    cudaGetSymbolAddress((void**)&qkv,  g_qkv);
    cudaGetSymbolAddress((void**)&att,  g_att);
    cudaGetSymbolAddress((void**)&wqkv, g_wqkv);
    cudaGetSymbolAddress((void**)&wout, g_wout);

    cudaFuncSetAttribute(gemm_f16<true>,  cudaFuncAttributeMaxDynamicSharedMemorySize, GEMM_SMEM);
    cudaFuncSetAttribute(gemm_f16<false>, cudaFuncAttributeMaxDynamicSharedMemorySize, GEMM_SMEM);
    cudaFuncSetAttribute(attn_mma, cudaFuncAttributeMaxDynamicSharedMemorySize, ATTN_SMEM);

    ln_kernel<<<ROWS / 8, 256>>>(x, gamma, beta, xn);
    convert_h<<<(DIMD * QKVW / 4 + 255) / 256, 256>>>(w_qkv, wqkv, DIMD * QKVW / 4);
    convert_h<<<(INNER * DIMD / 4 + 255) / 256, 256>>>(w_out, wout, INNER * DIMD / 4);
    gemm_f16<true><<<dim3(QKVW / 128, ROWS / 128), 256, GEMM_SMEM>>>(xn, wqkv, qkv, ROWS, QKVW, DIMD);
    attn_mma<<<dim3(SEQ / 128, HEADS, BATCH), 256, ATTN_SMEM>>>(qkv, att);
    gemm_f16<false><<<dim3(DIMD / 128, ROWS / 128), 256, GEMM_SMEM>>>(att, wout, out, ROWS, DIMD, INNER);
}

// round 16
// speedup vs baseline: 1.0345x; 1.0345x over previous
#include <cuda_runtime.h>
#include <cuda_fp16.h>
#include <math.h>
#include <cstdint>

#define DIMD   1024
#define HEADS  16
#define DH     64
#define INNER  1024
#define BATCH  4
#define SEQ    2048
#define ROWS   (BATCH*SEQ)      // 8192
#define QKVW   (3*INNER)        // 3072

// Scratch (device globals). All fp16, NATURAL layouts.
__device__ __half g_xn  [ROWS*DIMD];
__device__ __half g_qkv [ROWS*QKVW];
__device__ __half g_att [ROWS*INNER];
__device__ __half g_wqkv[DIMD*QKVW];    // [K][N] natural (fp16 copy)
__device__ __half g_wout[INNER*DIMD];   // [K][N] natural (fp16 copy)

__device__ __forceinline__ void mma_f16(float* d, const uint32_t* a, const uint32_t* b) {
    asm volatile(
        "mma.sync.aligned.m16n8k16.row.col.f32.f16.f16.f32 "
        "{%0,%1,%2,%3}, {%4,%5,%6,%7}, {%8,%9}, {%0,%1,%2,%3};"
        : "+f"(d[0]), "+f"(d[1]), "+f"(d[2]), "+f"(d[3])
        : "r"(a[0]), "r"(a[1]), "r"(a[2]), "r"(a[3]), "r"(b[0]), "r"(b[1]));
}

__device__ __forceinline__ void ldmx4(uint32_t& r0, uint32_t& r1, uint32_t& r2,
                                      uint32_t& r3, uint32_t addr) {
    asm volatile("ldmatrix.sync.aligned.m8n8.x4.shared.b16 {%0,%1,%2,%3}, [%4];"
                 : "=r"(r0), "=r"(r1), "=r"(r2), "=r"(r3) : "r"(addr));
}
__device__ __forceinline__ void ldmx4t(uint32_t& r0, uint32_t& r1, uint32_t& r2,
                                       uint32_t& r3, uint32_t addr) {
    asm volatile("ldmatrix.sync.aligned.m8n8.x4.trans.shared.b16 {%0,%1,%2,%3}, [%4];"
                 : "=r"(r0), "=r"(r1), "=r"(r2), "=r"(r3) : "r"(addr));
}

__device__ __forceinline__ void cp_async16(uint32_t smem_dst, const void* gmem_src) {
    asm volatile("cp.async.cg.shared.global [%0], [%1], 16;" :: "r"(smem_dst), "l"(gmem_src));
}
#define CP_COMMIT() asm volatile("cp.async.commit_group;" ::: "memory")
#define CP_WAIT(n)  asm volatile("cp.async.wait_group %0;" :: "n"(n) : "memory")

__device__ __forceinline__ uint32_t h2u(__half2 h) { return *reinterpret_cast<uint32_t*>(&h); }
__device__ __forceinline__ uint32_t packh2(float a, float b) {
    return h2u(__floats2half2_rn(a, b));
}

// ===========================================================================
// Fused prologue: blocks [0,ROWS) = LayerNorm (block-per-row, R14 body);
// blocks [ROWS, ROWS+3072) = w_qkv fp32->fp16; rest = w_out fp32->fp16.
// ===========================================================================
#define WQKV_BLKS (DIMD * QKVW / 4 / 256)    // 3072
#define WOUT_BLKS (INNER * DIMD / 4 / 256)   // 1024
#define PRO_BLKS  (ROWS + WQKV_BLKS + WOUT_BLKS)

__global__ void prologue_kernel(const float* __restrict__ x,
                                const float* __restrict__ gamma,
                                const float* __restrict__ beta,
                                const float* __restrict__ w_qkv,
                                const float* __restrict__ w_out,
                                __half* __restrict__ xn,
                                __half* __restrict__ wqkv,
                                __half* __restrict__ wout) {
    int tid = threadIdx.x;
    if (blockIdx.x >= ROWS) {
        // ---- weight convert path
        const float* in;
        __half* out;
        int i;
        if (blockIdx.x < ROWS + WQKV_BLKS) {
            in = w_qkv; out = wqkv;
            i = (blockIdx.x - ROWS) * 256 + tid;
        } else {
            in = w_out; out = wout;
            i = (blockIdx.x - ROWS - WQKV_BLKS) * 256 + tid;
        }
        float4 v = reinterpret_cast<const float4*>(in)[i];
        uint2 o2;
        o2.x = packh2(v.x, v.y);
        o2.y = packh2(v.z, v.w);
        *reinterpret_cast<uint2*>(out + (size_t)i * 4) = o2;
        return;
    }
    // ---- LayerNorm path (R14: block-per-row, 256 threads, float4)
    int row = blockIdx.x;
    const float4* xr = reinterpret_cast<const float4*>(x + (size_t)row * DIMD);
    float4 v = xr[tid];
    float s  = v.x + v.y + v.z + v.w;
    float ss = v.x*v.x + v.y*v.y + v.z*v.z + v.w*v.w;
    #pragma unroll
    for (int o = 16; o > 0; o >>= 1) {
        s  += __shfl_xor_sync(0xFFFFFFFFu, s,  o);
        ss += __shfl_xor_sync(0xFFFFFFFFu, ss, o);
    }
    __shared__ float rs[8], rq[8];
    int w = tid >> 5, l = tid & 31;
    if (l == 0) { rs[w] = s; rq[w] = ss; }
    __syncthreads();
    if (w == 0) {
        s  = (l < 8) ? rs[l] : 0.f;
        ss = (l < 8) ? rq[l] : 0.f;
        #pragma unroll
        for (int o = 4; o > 0; o >>= 1) {
            s  += __shfl_xor_sync(0xFFFFFFFFu, s,  o);
            ss += __shfl_xor_sync(0xFFFFFFFFu, ss, o);
        }
        if (l == 0) { rs[0] = s; rq[0] = ss; }
    }
    __syncthreads();
    float mu   = rs[0] * (1.0f / DIMD);
    float var  = rq[0] * (1.0f / DIMD) - mu * mu;
    float rstd = rsqrtf(var + 1e-5f);
    float4 g4 = reinterpret_cast<const float4*>(gamma)[tid];
    float4 b4 = reinterpret_cast<const float4*>(beta)[tid];
    uint2 o2;
    o2.x = packh2((v.x - mu) * rstd * g4.x + b4.x, (v.y - mu) * rstd * g4.y + b4.y);
    o2.y = packh2((v.z - mu) * rstd * g4.z + b4.z, (v.w - mu) * rstd * g4.w + b4.w);
    *reinterpret_cast<uint2*>(xn + (size_t)row * DIMD + tid * 4) = o2;
}

// ===========================================================================
// fp16 mma.sync GEMM, cp.async 3-stage ring, one barrier per phase.
// C[M,Nn] = A[M,K] @ W[K,Nn]. A natural [M][K]; W natural [K][Nn].
// (byte-identical to R14)
// ===========================================================================
#define GBK   64
#define GSTR  72
#define BSTR  136
#define GTILEA (128 * GSTR)
#define GTILEB (64 * BSTR)
#define GEMM_SMEM ((3 * GTILEA + 3 * GTILEB) * 2)   // 107520 B

template <bool HALF_OUT>
__global__ __launch_bounds__(256, 2)
void gemm_f16(const __half* __restrict__ A, const __half* __restrict__ W,
              void* __restrict__ Cv, int M, int Nn, int K) {
    extern __shared__ __half smh[];

    int tid  = threadIdx.x;
    int lane = tid & 31;
    int wid  = tid >> 5;
    int wm   = wid >> 2;
    int wn   = wid & 3;

    const __half* Ab = A + (size_t)blockIdx.y * 128 * K;
    const __half* Wb = W + blockIdx.x * 128;

    float acc[4][4][4];
    #pragma unroll
    for (int i = 0; i < 4; i++)
        #pragma unroll
        for (int j = 0; j < 4; j++)
            #pragma unroll
            for (int k = 0; k < 4; k++) acc[i][j][k] = 0.f;

    const int nchunks = K / GBK;
    uint32_t smbase = (uint32_t)__cvta_generic_to_shared(smh);

    auto stage = [&](int c) {
        int buf = c % 3;
        uint32_t sA = smbase + (buf * GTILEA) * 2;
        uint32_t sB = smbase + (3 * GTILEA + buf * GTILEB) * 2;
        const __half* Ac = Ab + c * GBK;
        const __half* Wc = Wb + (size_t)(c * GBK) * Nn;
        #pragma unroll
        for (int i = 0; i < 4; i++) {
            int idx = i * 256 + tid;
            int m = idx >> 3, k8 = (idx & 7) << 3;
            cp_async16(sA + (m * GSTR + k8) * 2, Ac + (size_t)m * K + k8);
            int kr = idx >> 4, n8 = (idx & 15) << 3;
            cp_async16(sB + (kr * BSTR + n8) * 2, Wc + (size_t)kr * Nn + n8);
        }
    };

    stage(0); CP_COMMIT();
    stage(1); CP_COMMIT();

    int r  = lane >> 2;
    int cq = lane & 3;
    int arow = lane & 15, akoff = (lane >> 4) << 3;
    int sub = lane >> 3;
    int blb = ((sub & 1) * 8 + (lane & 7)) * BSTR + (sub >> 1) * 8;

    for (int c = 0; c < nchunks; c++) {
        if (c + 1 < nchunks) { CP_WAIT(1); } else { CP_WAIT(0); }
        __syncthreads();
        if (c + 2 < nchunks) { stage(c + 2); CP_COMMIT(); }

        int buf = c % 3;
        uint32_t sAu = smbase + (buf * GTILEA) * 2;
        uint32_t sBu = smbase + (3 * GTILEA + buf * GTILEB) * 2;

        #pragma unroll
        for (int ks = 0; ks < 4; ks++) {
            uint32_t a[4][4], b[2][4];
            #pragma unroll
            for (int mt = 0; mt < 4; mt++) {
                uint32_t addr = sAu + (((wm * 64 + mt * 16 + arow) * GSTR) + ks * 16 + akoff) * 2;
                ldmx4(a[mt][0], a[mt][1], a[mt][2], a[mt][3], addr);
            }
            #pragma unroll
            for (int np = 0; np < 2; np++) {
                uint32_t addr = sBu + (ks * 16 * BSTR + wn * 32 + np * 16 + blb) * 2;
                ldmx4t(b[np][0], b[np][1], b[np][2], b[np][3], addr);
            }
            #pragma unroll
            for (int mt = 0; mt < 4; mt++)
                #pragma unroll
                for (int nt = 0; nt < 4; nt++)
                    mma_f16(acc[mt][nt], a[mt], &b[nt >> 1][(nt & 1) * 2]);
        }
    }

    #pragma unroll
    for (int mt = 0; mt < 4; mt++) {
        int row0 = blockIdx.y * 128 + wm * 64 + mt * 16 + r;
        #pragma unroll
        for (int nt = 0; nt < 4; nt++) {
            int col0 = blockIdx.x * 128 + wn * 32 + nt * 8 + cq * 2;
            if (HALF_OUT) {
                __half* C = (__half*)Cv;
                *reinterpret_cast<uint32_t*>(C + (size_t)row0 * Nn + col0) =
                    packh2(acc[mt][nt][0], acc[mt][nt][1]);
                *reinterpret_cast<uint32_t*>(C + (size_t)(row0 + 8) * Nn + col0) =
                    packh2(acc[mt][nt][2], acc[mt][nt][3]);
            } else {
                float* C = (float*)Cv;
                *reinterpret_cast<float2*>(C + (size_t)row0 * Nn + col0) =
                    make_float2(acc[mt][nt][0], acc[mt][nt][1]);
                *reinterpret_cast<float2*>(C + (size_t)(row0 + 8) * Nn + col0) =
                    make_float2(acc[mt][nt][2], acc[mt][nt][3]);
            }
        }
    }
}

// ===========================================================================
// Flash attention fp16 mma, register-resident P, 2-stage ring, one barrier
// per phase, 2 CTAs/SM, exp2 softmax. (byte-identical to R14)
// ===========================================================================
#define KSTR 72
#define KTILE (64 * KSTR)
#define ASM_Q (4 * KTILE)
#define QSTR 72
#define ATTN_SMEM ((4 * KTILE + 128 * QSTR) * 2)   // 55296 B -> 2 CTAs/SM

__global__ __launch_bounds__(256, 2)
void attn_mma(const __half* __restrict__ qkv, __half* __restrict__ att) {
    extern __shared__ __half smh[];

    int tid = threadIdx.x, lane = tid & 31, wid = tid >> 5;
    int r = lane >> 2, cq = lane & 3;
    int qt = gridDim.x - 1 - blockIdx.x;     // longest tiles first
    int h = blockIdx.y, b = blockIdx.z;
    int q0 = qt * 128;

    const __half* qbase = qkv + (size_t)b * SEQ * QKVW + h * DH;
    const __half* kbase = qbase + INNER;
    const __half* vbase = qbase + 2 * INNER;

    uint32_t smb = (uint32_t)__cvta_generic_to_shared(smh);
    uint32_t sQu = smb + ASM_Q * 2;

    const int nchunk = 2 * qt + 2;

    auto stage = [&](int c) {
        int buf = c & 1;
        uint32_t sK = smb + (buf * KTILE) * 2;
        uint32_t sV = smb + ((2 + buf) * KTILE) * 2;
        const __half* kc = kbase + (size_t)c * 64 * QKVW;
        const __half* vc = vbase + (size_t)c * 64 * QKVW;
        #pragma unroll
        for (int i = 0; i < 2; i++) {
            int idx = i * 256 + tid;
            int row = idx >> 3, d8 = (idx & 7) << 3;
            cp_async16(sK + (row * KSTR + d8) * 2, kc + (size_t)row * QKVW + d8);
            cp_async16(sV + (row * KSTR + d8) * 2, vc + (size_t)row * QKVW + d8);
        }
    };

    #pragma unroll
    for (int i = 0; i < 4; i++) {
        int idx = i * 256 + tid;
        int row = idx >> 3, d8 = (idx & 7) << 3;
        cp_async16(sQu + (row * QSTR + d8) * 2, qbase + (size_t)(q0 + row) * QKVW + d8);
    }
    stage(0); CP_COMMIT();

    int arow = lane & 15, akoff = (lane >> 4) << 3;
    int brow = ((lane >> 4) << 3) + (lane & 7), bkoff = ((lane >> 3) & 1) << 3;
    int sub = lane >> 3;
    int vlb = ((sub & 1) * 8 + (lane & 7)) * KSTR + (sub >> 1) * 8;

    uint32_t qf[4][4];
    float m0 = -1e30f, m1 = -1e30f, l0 = 0.f, l1 = 0.f;
    float o[8][4];
    #pragma unroll
    for (int nt = 0; nt < 8; nt++)
        #pragma unroll
        for (int j = 0; j < 4; j++) o[nt][j] = 0.f;

    const __half2 qsc = __floats2half2_rn(0.125f * 1.44269504f, 0.125f * 1.44269504f);

    for (int c = 0; c < nchunk; c++) {
        CP_WAIT(0);
        __syncthreads();
        if (c + 1 < nchunk) { stage(c + 1); CP_COMMIT(); }

        if (c == 0) {
            #pragma unroll
            for (int kt = 0; kt < 4; kt++) {
                uint32_t addr = sQu + (((wid * 16 + arow) * QSTR) + kt * 16 + akoff) * 2;
                ldmx4(qf[kt][0], qf[kt][1], qf[kt][2], qf[kt][3], addr);
                #pragma unroll
                for (int j = 0; j < 4; j++)
                    qf[kt][j] = h2u(__hmul2(*reinterpret_cast<__half2*>(&qf[kt][j]), qsc));
            }
        }

        int buf = c & 1;
        uint32_t sKu = smb + (buf * KTILE) * 2;
        uint32_t sVu = smb + ((2 + buf) * KTILE) * 2;

        int wrow0 = q0 + wid * 16;
        if (wrow0 + 15 >= c * 64) {
            float s[8][4];
            #pragma unroll
            for (int nt = 0; nt < 8; nt++)
                #pragma unroll
                for (int j = 0; j < 4; j++) s[nt][j] = 0.f;
            #pragma unroll
            for (int kt = 0; kt < 4; kt++) {
                #pragma unroll
                for (int np = 0; np < 4; np++) {
                    uint32_t b0, b1, b2, b3;
                    uint32_t addr = sKu + (((np * 16 + brow) * KSTR) + kt * 16 + bkoff) * 2;
                    ldmx4(b0, b1, b2, b3, addr);
                    uint32_t bfa[2] = { b0, b1 };
                    uint32_t bfb[2] = { b2, b3 };
                    mma_f16(s[2 * np],     qf[kt], bfa);
                    mma_f16(s[2 * np + 1], qf[kt], bfb);
                }
            }

            if (c * 64 + 63 > wrow0) {
                int row_a = wrow0 + r, row_b = wrow0 + r + 8;
                #pragma unroll
                for (int nt = 0; nt < 8; nt++) {
                    int col = c * 64 + nt * 8 + 2 * cq;
                    if (col     > row_a) s[nt][0] = -1e30f;
                    if (col + 1 > row_a) s[nt][1] = -1e30f;
                    if (col     > row_b) s[nt][2] = -1e30f;
                    if (col + 1 > row_b) s[nt][3] = -1e30f;
                }
            }

            float mt0 = -1e30f, mt1 = -1e30f;
            #pragma unroll
            for (int nt = 0; nt < 8; nt++) {
                mt0 = fmaxf(mt0, fmaxf(s[nt][0], s[nt][1]));
                mt1 = fmaxf(mt1, fmaxf(s[nt][2], s[nt][3]));
            }
            mt0 = fmaxf(mt0, __shfl_xor_sync(0xFFFFFFFFu, mt0, 1));
            mt0 = fmaxf(mt0, __shfl_xor_sync(0xFFFFFFFFu, mt0, 2));
            mt1 = fmaxf(mt1, __shfl_xor_sync(0xFFFFFFFFu, mt1, 1));
            mt1 = fmaxf(mt1, __shfl_xor_sync(0xFFFFFFFFu, mt1, 2));

            float mn0 = fmaxf(m0, mt0), mn1 = fmaxf(m1, mt1);
            float a0 = exp2f(m0 - mn0), a1 = exp2f(m1 - mn1);
            m0 = mn0; m1 = mn1;
            float rs0 = 0.f, rs1 = 0.f;
            #pragma unroll
            for (int nt = 0; nt < 8; nt++) {
                s[nt][0] = exp2f(s[nt][0] - mn0);
                s[nt][1] = exp2f(s[nt][1] - mn0);
                s[nt][2] = exp2f(s[nt][2] - mn1);
                s[nt][3] = exp2f(s[nt][3] - mn1);
                rs0 += s[nt][0] + s[nt][1];
                rs1 += s[nt][2] + s[nt][3];
            }
            rs0 += __shfl_xor_sync(0xFFFFFFFFu, rs0, 1);
            rs0 += __shfl_xor_sync(0xFFFFFFFFu, rs0, 2);
            rs1 += __shfl_xor_sync(0xFFFFFFFFu, rs1, 1);
            rs1 += __shfl_xor_sync(0xFFFFFFFFu, rs1, 2);
            l0 = l0 * a0 + rs0;
            l1 = l1 * a1 + rs1;
            #pragma unroll
            for (int nt = 0; nt < 8; nt++) {
                o[nt][0] *= a0; o[nt][1] *= a0;
                o[nt][2] *= a1; o[nt][3] *= a1;
            }

            #pragma unroll
            for (int kt = 0; kt < 4; kt++) {
                uint32_t pf[4];
                pf[0] = packh2(s[2 * kt][0],     s[2 * kt][1]);
                pf[1] = packh2(s[2 * kt][2],     s[2 * kt][3]);
                pf[2] = packh2(s[2 * kt + 1][0], s[2 * kt + 1][1]);
                pf[3] = packh2(s[2 * kt + 1][2], s[2 * kt + 1][3]);
                #pragma unroll
                for (int ntp = 0; ntp < 4; ntp++) {
                    uint32_t b0a, b1a, b0b, b1b;
                    uint32_t addr = sVu + (vlb + kt * 16 * KSTR + ntp * 16) * 2;
                    ldmx4t(b0a, b1a, b0b, b1b, addr);
                    uint32_t bfa[2] = { b0a, b1a };
                    uint32_t bfb[2] = { b0b, b1b };
                    mma_f16(o[2 * ntp],     pf, bfa);
                    mma_f16(o[2 * ntp + 1], pf, bfb);
                }
            }
        }
    }

    float inv0 = 1.f / l0, inv1 = 1.f / l1;
    int row_a = q0 + wid * 16 + r, row_b = row_a + 8;
    #pragma unroll
    for (int nt = 0; nt < 8; nt++) {
        int col = h * DH + nt * 8 + 2 * cq;
        *reinterpret_cast<uint32_t*>(att + ((size_t)b * SEQ + row_a) * INNER + col) =
            packh2(o[nt][0] * inv0, o[nt][1] * inv0);
        *reinterpret_cast<uint32_t*>(att + ((size_t)b * SEQ + row_b) * INNER + col) =
            packh2(o[nt][2] * inv1, o[nt][3] * inv1);
    }
}

// ===========================================================================
extern "C" void kernel_launch(void* const* d_in, const int* in_sizes, int n_in,
                              void* d_out, int out_size) {
    const float* x     = (const float*)d_in[0];
    const float* gamma = (const float*)d_in[1];
    const float* beta  = (const float*)d_in[2];
    const float* w_qkv = (const float*)d_in[3];
    const float* w_out = (const float*)d_in[4];
    float* out = (float*)d_out;

    __half *xn, *qkv, *att, *wqkv, *wout;
    cudaGetSymbolAddress((void**)&xn,   g_xn);
    cudaGetSymbolAddress((void**)&qkv,  g_qkv);
    cudaGetSymbolAddress((void**)&att,  g_att);
    cudaGetSymbolAddress((void**)&wqkv, g_wqkv);
    cudaGetSymbolAddress((void**)&wout, g_wout);

    cudaFuncSetAttribute(gemm_f16<true>,  cudaFuncAttributeMaxDynamicSharedMemorySize, GEMM_SMEM);
    cudaFuncSetAttribute(gemm_f16<false>, cudaFuncAttributeMaxDynamicSharedMemorySize, GEMM_SMEM);
    cudaFuncSetAttribute(attn_mma, cudaFuncAttributeMaxDynamicSharedMemorySize, ATTN_SMEM);

    prologue_kernel<<<PRO_BLKS, 256>>>(x, gamma, beta, w_qkv, w_out, xn, wqkv, wout);
    gemm_f16<true><<<dim3(QKVW / 128, ROWS / 128), 256, GEMM_SMEM>>>(xn, wqkv, qkv, ROWS, QKVW, DIMD);
    attn_mma<<<dim3(SEQ / 128, HEADS, BATCH), 256, ATTN_SMEM>>>(qkv, att);
    gemm_f16<false><<<dim3(DIMD / 128, ROWS / 128), 256, GEMM_SMEM>>>(att, wout, out, ROWS, DIMD, INNER);
}

// round 17
// speedup vs baseline: 1.0532x; 1.0181x over previous
#include <cuda_runtime.h>
#include <cuda_fp16.h>
#include <math.h>
#include <cstdint>

#define DIMD   1024
#define HEADS  16
#define DH     64
#define INNER  1024
#define BATCH  4
#define SEQ    2048
#define ROWS   (BATCH*SEQ)      // 8192
#define QKVW   (3*INNER)        // 3072

// Scratch (device globals). fp16. Weights stored TRANSPOSED [N][K].
__device__ __half g_xn   [ROWS*DIMD];
__device__ __half g_qkv  [ROWS*QKVW];
__device__ __half g_att  [ROWS*INNER];
__device__ __half g_wqkvT[QKVW*DIMD];
__device__ __half g_woutT[DIMD*INNER];

__device__ __forceinline__ void mma_f16(float* d, const uint32_t* a, const uint32_t* b) {
    asm volatile(
        "mma.sync.aligned.m16n8k16.row.col.f32.f16.f16.f32 "
        "{%0,%1,%2,%3}, {%4,%5,%6,%7}, {%8,%9}, {%0,%1,%2,%3};"
        : "+f"(d[0]), "+f"(d[1]), "+f"(d[2]), "+f"(d[3])
        : "r"(a[0]), "r"(a[1]), "r"(a[2]), "r"(a[3]), "r"(b[0]), "r"(b[1]));
}

__device__ __forceinline__ void ldmx4(uint32_t& r0, uint32_t& r1, uint32_t& r2,
                                      uint32_t& r3, uint32_t addr) {
    asm volatile("ldmatrix.sync.aligned.m8n8.x4.shared.b16 {%0,%1,%2,%3}, [%4];"
                 : "=r"(r0), "=r"(r1), "=r"(r2), "=r"(r3) : "r"(addr));
}
__device__ __forceinline__ void ldmx4t(uint32_t& r0, uint32_t& r1, uint32_t& r2,
                                       uint32_t& r3, uint32_t addr) {
    asm volatile("ldmatrix.sync.aligned.m8n8.x4.trans.shared.b16 {%0,%1,%2,%3}, [%4];"
                 : "=r"(r0), "=r"(r1), "=r"(r2), "=r"(r3) : "r"(addr));
}

__device__ __forceinline__ void cp_async16(uint32_t smem_dst, const void* gmem_src) {
    asm volatile("cp.async.cg.shared.global [%0], [%1], 16;" :: "r"(smem_dst), "l"(gmem_src));
}
#define CP_COMMIT() asm volatile("cp.async.commit_group;" ::: "memory")
#define CP_WAIT(n)  asm volatile("cp.async.wait_group %0;" :: "n"(n) : "memory")

__device__ __forceinline__ uint32_t h2u(__half2 h) { return *reinterpret_cast<uint32_t*>(&h); }
__device__ __forceinline__ uint32_t packh2(float a, float b) {
    return h2u(__floats2half2_rn(a, b));
}

// ===========================================================================
// Fused prologue:
//   blocks [0, ROWS)            : LayerNorm (block-per-row)
//   blocks [ROWS, +3072)        : w_qkv [1024][3072] -> wqkvT [3072][1024] fp16
//   blocks [ROWS+3072, +1024)   : w_out [1024][1024] -> woutT [1024][1024] fp16
// ===========================================================================
#define WQKV_TB 3072     // (3072/32)*(1024/32)
#define WOUT_TB 1024     // (1024/32)*(1024/32)
#define PRO_BLKS (ROWS + WQKV_TB + WOUT_TB)

__global__ void prologue_kernel(const float* __restrict__ x,
                                const float* __restrict__ gamma,
                                const float* __restrict__ beta,
                                const float* __restrict__ w_qkv,
                                const float* __restrict__ w_out,
                                __half* __restrict__ xn,
                                __half* __restrict__ wqkvT,
                                __half* __restrict__ woutT) {
    int tid = threadIdx.x;
    if (blockIdx.x >= ROWS) {
        // ---- transpose-cvt path (32x32 tile, 256 thr as 32x8)
        const float* in; __half* out;
        int R, Cc, bi;
        if (blockIdx.x < ROWS + WQKV_TB) {
            in = w_qkv; out = wqkvT; R = DIMD; Cc = QKVW;
            bi = blockIdx.x - ROWS;
        } else {
            in = w_out; out = woutT; R = INNER; Cc = DIMD;
            bi = blockIdx.x - ROWS - WQKV_TB;
        }
        int ntx = Cc >> 5;
        int c0 = (bi % ntx) * 32, r0 = (bi / ntx) * 32;
        int xx = tid & 31, yy = tid >> 5;
        __shared__ float t[32][33];
        #pragma unroll
        for (int i = 0; i < 32; i += 8)
            t[yy + i][xx] = in[(size_t)(r0 + yy + i) * Cc + c0 + xx];
        __syncthreads();
        #pragma unroll
        for (int i = 0; i < 32; i += 8)
            out[(size_t)(c0 + yy + i) * R + r0 + xx] = __float2half_rn(t[xx][yy + i]);
        return;
    }
    // ---- LayerNorm path (block-per-row, 256 threads, float4)
    int row = blockIdx.x;
    const float4* xr = reinterpret_cast<const float4*>(x + (size_t)row * DIMD);
    float4 v = xr[tid];
    float s  = v.x + v.y + v.z + v.w;
    float ss = v.x*v.x + v.y*v.y + v.z*v.z + v.w*v.w;
    #pragma unroll
    for (int o = 16; o > 0; o >>= 1) {
        s  += __shfl_xor_sync(0xFFFFFFFFu, s,  o);
        ss += __shfl_xor_sync(0xFFFFFFFFu, ss, o);
    }
    __shared__ float rs[8], rq[8];
    int w = tid >> 5, l = tid & 31;
    if (l == 0) { rs[w] = s; rq[w] = ss; }
    __syncthreads();
    if (w == 0) {
        s  = (l < 8) ? rs[l] : 0.f;
        ss = (l < 8) ? rq[l] : 0.f;
        #pragma unroll
        for (int o = 4; o > 0; o >>= 1) {
            s  += __shfl_xor_sync(0xFFFFFFFFu, s,  o);
            ss += __shfl_xor_sync(0xFFFFFFFFu, ss, o);
        }
        if (l == 0) { rs[0] = s; rq[0] = ss; }
    }
    __syncthreads();
    float mu   = rs[0] * (1.0f / DIMD);
    float var  = rq[0] * (1.0f / DIMD) - mu * mu;
    float rstd = rsqrtf(var + 1e-5f);
    float4 g4 = reinterpret_cast<const float4*>(gamma)[tid];
    float4 b4 = reinterpret_cast<const float4*>(beta)[tid];
    uint2 o2;
    o2.x = packh2((v.x - mu) * rstd * g4.x + b4.x, (v.y - mu) * rstd * g4.y + b4.y);
    o2.y = packh2((v.z - mu) * rstd * g4.z + b4.z, (v.w - mu) * rstd * g4.w + b4.w);
    *reinterpret_cast<uint2*>(xn + (size_t)row * DIMD + tid * 4) = o2;
}

// ===========================================================================
// fp16 mma.sync GEMM (R13 form): cp.async 3-stage ring, one barrier/phase,
// C[M,Nn] = A[M,K] @ BT[Nn,K]^T, both operands ldmatrix.x4 (non-trans).
// CTA 128x128, 256 thr, warp 64x32, GBK=64.
// ===========================================================================
#define GBK   64
#define GSTR  72
#define GTILE (128 * GSTR)
#define GEMM_SMEM (6 * GTILE * 2)         // 110592 B

template <bool HALF_OUT>
__global__ __launch_bounds__(256, 2)
void gemm_f16(const __half* __restrict__ A, const __half* __restrict__ BT,
              void* __restrict__ Cv, int M, int Nn, int K) {
    extern __shared__ __half smh[];

    int tid  = threadIdx.x;
    int lane = tid & 31;
    int wid  = tid >> 5;
    int wm   = wid >> 2;
    int wn   = wid & 3;

    const __half* Ab = A  + (size_t)blockIdx.y * 128 * K;
    const __half* Bb = BT + (size_t)blockIdx.x * 128 * K;

    float acc[4][4][4];
    #pragma unroll
    for (int i = 0; i < 4; i++)
        #pragma unroll
        for (int j = 0; j < 4; j++)
            #pragma unroll
            for (int k = 0; k < 4; k++) acc[i][j][k] = 0.f;

    const int nchunks = K / GBK;
    uint32_t smbase = (uint32_t)__cvta_generic_to_shared(smh);

    auto stage = [&](int c) {
        int buf = c % 3;
        uint32_t sA = smbase + (buf * GTILE) * 2;
        uint32_t sB = smbase + ((3 + buf) * GTILE) * 2;
        const __half* Ac = Ab + c * GBK;
        const __half* Bc = Bb + c * GBK;
        #pragma unroll
        for (int i = 0; i < 4; i++) {
            int idx = i * 256 + tid;
            int m = idx >> 3, k8 = (idx & 7) << 3;
            cp_async16(sA + (m * GSTR + k8) * 2, Ac + (size_t)m * K + k8);
            cp_async16(sB + (m * GSTR + k8) * 2, Bc + (size_t)m * K + k8);
        }
    };

    stage(0); CP_COMMIT();
    stage(1); CP_COMMIT();

    int r  = lane >> 2;
    int cq = lane & 3;
    int arow = lane & 15, akoff = (lane >> 4) << 3;
    int brow = ((lane >> 4) << 3) + (lane & 7), bkoff = ((lane >> 3) & 1) << 3;

    for (int c = 0; c < nchunks; c++) {
        if (c + 1 < nchunks) { CP_WAIT(1); } else { CP_WAIT(0); }
        __syncthreads();
        if (c + 2 < nchunks) { stage(c + 2); CP_COMMIT(); }

        int buf = c % 3;
        uint32_t sAu = smbase + (buf * GTILE) * 2;
        uint32_t sBu = smbase + ((3 + buf) * GTILE) * 2;

        #pragma unroll
        for (int ks = 0; ks < 4; ks++) {
            uint32_t a[4][4], b[2][4];
            #pragma unroll
            for (int mt = 0; mt < 4; mt++) {
                uint32_t addr = sAu + (((wm * 64 + mt * 16 + arow) * GSTR) + ks * 16 + akoff) * 2;
                ldmx4(a[mt][0], a[mt][1], a[mt][2], a[mt][3], addr);
            }
            #pragma unroll
            for (int np = 0; np < 2; np++) {
                uint32_t addr = sBu + (((wn * 32 + np * 16 + brow) * GSTR) + ks * 16 + bkoff) * 2;
                ldmx4(b[np][0], b[np][1], b[np][2], b[np][3], addr);
            }
            #pragma unroll
            for (int mt = 0; mt < 4; mt++)
                #pragma unroll
                for (int nt = 0; nt < 4; nt++)
                    mma_f16(acc[mt][nt], a[mt], &b[nt >> 1][(nt & 1) * 2]);
        }
    }

    #pragma unroll
    for (int mt = 0; mt < 4; mt++) {
        int row0 = blockIdx.y * 128 + wm * 64 + mt * 16 + r;
        #pragma unroll
        for (int nt = 0; nt < 4; nt++) {
            int col0 = blockIdx.x * 128 + wn * 32 + nt * 8 + cq * 2;
            if (HALF_OUT) {
                __half* C = (__half*)Cv;
                *reinterpret_cast<uint32_t*>(C + (size_t)row0 * Nn + col0) =
                    packh2(acc[mt][nt][0], acc[mt][nt][1]);
                *reinterpret_cast<uint32_t*>(C + (size_t)(row0 + 8) * Nn + col0) =
                    packh2(acc[mt][nt][2], acc[mt][nt][3]);
            } else {
                float* C = (float*)Cv;
                *reinterpret_cast<float2*>(C + (size_t)row0 * Nn + col0) =
                    make_float2(acc[mt][nt][0], acc[mt][nt][1]);
                *reinterpret_cast<float2*>(C + (size_t)(row0 + 8) * Nn + col0) =
                    make_float2(acc[mt][nt][2], acc[mt][nt][3]);
            }
        }
    }
}

// ===========================================================================
// Flash attention fp16 mma (R14/R16 body, unchanged): register-resident P,
// 2-stage ring, one barrier per phase, 2 CTAs/SM, exp2 softmax.
// ===========================================================================
#define KSTR 72
#define KTILE (64 * KSTR)
#define ASM_Q (4 * KTILE)
#define QSTR 72
#define ATTN_SMEM ((4 * KTILE + 128 * QSTR) * 2)   // 55296 B

__global__ __launch_bounds__(256, 2)
void attn_mma(const __half* __restrict__ qkv, __half* __restrict__ att) {
    extern __shared__ __half smh[];

    int tid = threadIdx.x, lane = tid & 31, wid = tid >> 5;
    int r = lane >> 2, cq = lane & 3;
    int qt = gridDim.x - 1 - blockIdx.x;
    int h = blockIdx.y, b = blockIdx.z;
    int q0 = qt * 128;

    const __half* qbase = qkv + (size_t)b * SEQ * QKVW + h * DH;
    const __half* kbase = qbase + INNER;
    const __half* vbase = qbase + 2 * INNER;

    uint32_t smb = (uint32_t)__cvta_generic_to_shared(smh);
    uint32_t sQu = smb + ASM_Q * 2;

    const int nchunk = 2 * qt + 2;

    auto stage = [&](int c) {
        int buf = c & 1;
        uint32_t sK = smb + (buf * KTILE) * 2;
        uint32_t sV = smb + ((2 + buf) * KTILE) * 2;
        const __half* kc = kbase + (size_t)c * 64 * QKVW;
        const __half* vc = vbase + (size_t)c * 64 * QKVW;
        #pragma unroll
        for (int i = 0; i < 2; i++) {
            int idx = i * 256 + tid;
            int row = idx >> 3, d8 = (idx & 7) << 3;
            cp_async16(sK + (row * KSTR + d8) * 2, kc + (size_t)row * QKVW + d8);
            cp_async16(sV + (row * KSTR + d8) * 2, vc + (size_t)row * QKVW + d8);
        }
    };

    #pragma unroll
    for (int i = 0; i < 4; i++) {
        int idx = i * 256 + tid;
        int row = idx >> 3, d8 = (idx & 7) << 3;
        cp_async16(sQu + (row * QSTR + d8) * 2, qbase + (size_t)(q0 + row) * QKVW + d8);
    }
    stage(0); CP_COMMIT();

    int arow = lane & 15, akoff = (lane >> 4) << 3;
    int brow = ((lane >> 4) << 3) + (lane & 7), bkoff = ((lane >> 3) & 1) << 3;
    int sub = lane >> 3;
    int vlb = ((sub & 1) * 8 + (lane & 7)) * KSTR + (sub >> 1) * 8;

    uint32_t qf[4][4];
    float m0 = -1e30f, m1 = -1e30f, l0 = 0.f, l1 = 0.f;
    float o[8][4];
    #pragma unroll
    for (int nt = 0; nt < 8; nt++)
        #pragma unroll
        for (int j = 0; j < 4; j++) o[nt][j] = 0.f;

    const __half2 qsc = __floats2half2_rn(0.125f * 1.44269504f, 0.125f * 1.44269504f);

    for (int c = 0; c < nchunk; c++) {
        CP_WAIT(0);
        __syncthreads();
        if (c + 1 < nchunk) { stage(c + 1); CP_COMMIT(); }

        if (c == 0) {
            #pragma unroll
            for (int kt = 0; kt < 4; kt++) {
                uint32_t addr = sQu + (((wid * 16 + arow) * QSTR) + kt * 16 + akoff) * 2;
                ldmx4(qf[kt][0], qf[kt][1], qf[kt][2], qf[kt][3], addr);
                #pragma unroll
                for (int j = 0; j < 4; j++)
                    qf[kt][j] = h2u(__hmul2(*reinterpret_cast<__half2*>(&qf[kt][j]), qsc));
            }
        }

        int buf = c & 1;
        uint32_t sKu = smb + (buf * KTILE) * 2;
        uint32_t sVu = smb + ((2 + buf) * KTILE) * 2;

        int wrow0 = q0 + wid * 16;
        if (wrow0 + 15 >= c * 64) {
            float s[8][4];
            #pragma unroll
            for (int nt = 0; nt < 8; nt++)
                #pragma unroll
                for (int j = 0; j < 4; j++) s[nt][j] = 0.f;
            #pragma unroll
            for (int kt = 0; kt < 4; kt++) {
                #pragma unroll
                for (int np = 0; np < 4; np++) {
                    uint32_t b0, b1, b2, b3;
                    uint32_t addr = sKu + (((np * 16 + brow) * KSTR) + kt * 16 + bkoff) * 2;
                    ldmx4(b0, b1, b2, b3, addr);
                    uint32_t bfa[2] = { b0, b1 };
                    uint32_t bfb[2] = { b2, b3 };
                    mma_f16(s[2 * np],     qf[kt], bfa);
                    mma_f16(s[2 * np + 1], qf[kt], bfb);
                }
            }

            if (c * 64 + 63 > wrow0) {
                int row_a = wrow0 + r, row_b = wrow0 + r + 8;
                #pragma unroll
                for (int nt = 0; nt < 8; nt++) {
                    int col = c * 64 + nt * 8 + 2 * cq;
                    if (col     > row_a) s[nt][0] = -1e30f;
                    if (col + 1 > row_a) s[nt][1] = -1e30f;
                    if (col     > row_b) s[nt][2] = -1e30f;
                    if (col + 1 > row_b) s[nt][3] = -1e30f;
                }
            }

            float mt0 = -1e30f, mt1 = -1e30f;
            #pragma unroll
            for (int nt = 0; nt < 8; nt++) {
                mt0 = fmaxf(mt0, fmaxf(s[nt][0], s[nt][1]));
                mt1 = fmaxf(mt1, fmaxf(s[nt][2], s[nt][3]));
            }
            mt0 = fmaxf(mt0, __shfl_xor_sync(0xFFFFFFFFu, mt0, 1));
            mt0 = fmaxf(mt0, __shfl_xor_sync(0xFFFFFFFFu, mt0, 2));
            mt1 = fmaxf(mt1, __shfl_xor_sync(0xFFFFFFFFu, mt1, 1));
            mt1 = fmaxf(mt1, __shfl_xor_sync(0xFFFFFFFFu, mt1, 2));

            float mn0 = fmaxf(m0, mt0), mn1 = fmaxf(m1, mt1);
            float a0 = exp2f(m0 - mn0), a1 = exp2f(m1 - mn1);
            m0 = mn0; m1 = mn1;
            float rs0 = 0.f, rs1 = 0.f;
            #pragma unroll
            for (int nt = 0; nt < 8; nt++) {
                s[nt][0] = exp2f(s[nt][0] - mn0);
                s[nt][1] = exp2f(s[nt][1] - mn0);
                s[nt][2] = exp2f(s[nt][2] - mn1);
                s[nt][3] = exp2f(s[nt][3] - mn1);
                rs0 += s[nt][0] + s[nt][1];
                rs1 += s[nt][2] + s[nt][3];
            }
            rs0 += __shfl_xor_sync(0xFFFFFFFFu, rs0, 1);
            rs0 += __shfl_xor_sync(0xFFFFFFFFu, rs0, 2);
            rs1 += __shfl_xor_sync(0xFFFFFFFFu, rs1, 1);
            rs1 += __shfl_xor_sync(0xFFFFFFFFu, rs1, 2);
            l0 = l0 * a0 + rs0;
            l1 = l1 * a1 + rs1;
            #pragma unroll
            for (int nt = 0; nt < 8; nt++) {
                o[nt][0] *= a0; o[nt][1] *= a0;
                o[nt][2] *= a1; o[nt][3] *= a1;
            }

            #pragma unroll
            for (int kt = 0; kt < 4; kt++) {
                uint32_t pf[4];
                pf[0] = packh2(s[2 * kt][0],     s[2 * kt][1]);
                pf[1] = packh2(s[2 * kt][2],     s[2 * kt][3]);
                pf[2] = packh2(s[2 * kt + 1][0], s[2 * kt + 1][1]);
                pf[3] = packh2(s[2 * kt + 1][2], s[2 * kt + 1][3]);
                #pragma unroll
                for (int ntp = 0; ntp < 4; ntp++) {
                    uint32_t b0a, b1a, b0b, b1b;
                    uint32_t addr = sVu + (vlb + kt * 16 * KSTR + ntp * 16) * 2;
                    ldmx4t(b0a, b1a, b0b, b1b, addr);
                    uint32_t bfa[2] = { b0a, b1a };
                    uint32_t bfb[2] = { b0b, b1b };
                    mma_f16(o[2 * ntp],     pf, bfa);
                    mma_f16(o[2 * ntp + 1], pf, bfb);
                }
            }
        }
    }

    float inv0 = 1.f / l0, inv1 = 1.f / l1;
    int row_a = q0 + wid * 16 + r, row_b = row_a + 8;
    #pragma unroll
    for (int nt = 0; nt < 8; nt++) {
        int col = h * DH + nt * 8 + 2 * cq;
        *reinterpret_cast<uint32_t*>(att + ((size_t)b * SEQ + row_a) * INNER + col) =
            packh2(o[nt][0] * inv0, o[nt][1] * inv0);
        *reinterpret_cast<uint32_t*>(att + ((size_t)b * SEQ + row_b) * INNER + col) =
            packh2(o[nt][2] * inv1, o[nt][3] * inv1);
    }
}

// ===========================================================================
extern "C" void kernel_launch(void* const* d_in, const int* in_sizes, int n_in,
                              void* d_out, int out_size) {
    const float* x     = (const float*)d_in[0];
    const float* gamma = (const float*)d_in[1];
    const float* beta  = (const float*)d_in[2];
    const float* w_qkv = (const float*)d_in[3];
    const float* w_out = (const float*)d_in[4];
    float* out = (float*)d_out;

    __half *xn, *qkv, *att, *wqkvT, *woutT;
    cudaGetSymbolAddress((void**)&xn,    g_xn);
    cudaGetSymbolAddress((void**)&qkv,   g_qkv);
    cudaGetSymbolAddress((void**)&att,   g_att);
    cudaGetSymbolAddress((void**)&wqkvT, g_wqkvT);
    cudaGetSymbolAddress((void**)&woutT, g_woutT);

    cudaFuncSetAttribute(gemm_f16<true>,  cudaFuncAttributeMaxDynamicSharedMemorySize, GEMM_SMEM);
    cudaFuncSetAttribute(gemm_f16<false>, cudaFuncAttributeMaxDynamicSharedMemorySize, GEMM_SMEM);
    cudaFuncSetAttribute(attn_mma, cudaFuncAttributeMaxDynamicSharedMemorySize, ATTN_SMEM);

    prologue_kernel<<<PRO_BLKS, 256>>>(x, gamma, beta, w_qkv, w_out, xn, wqkvT, woutT);
    gemm_f16<true><<<dim3(QKVW / 128, ROWS / 128), 256, GEMM_SMEM>>>(xn, wqkvT, qkv, ROWS, QKVW, DIMD);
    attn_mma<<<dim3(SEQ / 128, HEADS, BATCH), 256, ATTN_SMEM>>>(qkv, att);
    gemm_f16<false><<<dim3(DIMD / 128, ROWS / 128), 256, GEMM_SMEM>>>(att, woutT, out, ROWS, DIMD, INNER);
}